// round 14
// baseline (speedup 1.0000x reference)
#include <cuda_runtime.h>
#include <cuda_fp16.h>
#include <cuda_bf16.h>
#include <math.h>
#include <stdint.h>

#define BATCH 4
#define CDIM  256
#define CQK   32
#define NPIX  4096   // 64*64
#define MROWS 320    // 32 (Q) + 32 (K) + 256 (V)
#define LOG2E 1.4426950408889634f
#define ONES_H2 0x3C003C00u   // half2(1.0, 1.0)

// fp16 scratch (static device globals: allowed)
// g_Kh / g_VhT stored 32-wide K-PERMUTED along the contraction dim: within
// each 32-element block, pair p (elements 2p,2p+1) sits at half-offset
// (p&3)*8 + (p>>2)*2. A thread's uint4 at halves 8t..8t+7 then holds
// (b0,b1) for TWO consecutive k-steps -> one LDS.128 feeds 2 MMAs.
__device__ __half g_Qh[BATCH * NPIX * CQK];    // Q pre-scaled by log2(e); UNPERMUTED
__device__ __half g_Kh[BATCH * NPIX * CQK];    // permuted along d (32)
__device__ __half g_VhT[(size_t)BATCH * CDIM * NPIX];   // [B][C][N], permuted along N 32-blocks
__device__ __half g_xhT[(size_t)BATCH * NPIX * CDIM];   // [B][N][C]
__device__ __half g_Wh[MROWS * CDIM];                   // Wq|Wk|Wv stacked
__device__ float  g_ball[MROWS];

// ---------------------------------------------------------------------------
// helpers (defined BEFORE all uses)
// ---------------------------------------------------------------------------
__device__ __forceinline__ int perm32(int n)   // n even; 32-wide permuted position
{
    const int p = (n >> 1) & 15;
    return (n & ~31) + (p & 3) * 8 + (p >> 2) * 2;
}

// pack (lo, hi) fp32 -> half2, then 2^x elementwise. Returns half2 bits.
__device__ __forceinline__ uint32_t ex2_h2(float lo, float hi)
{
    uint32_t h;
    asm("cvt.rn.f16x2.f32 %0, %1, %2;" : "=r"(h) : "f"(hi), "f"(lo));
    asm("ex2.approx.f16x2 %0, %0;" : "+r"(h));
    return h;
}

__device__ __forceinline__ void mma16816(
    float& c0, float& c1, float& c2, float& c3,
    uint32_t a0, uint32_t a1, uint32_t a2, uint32_t a3,
    uint32_t b0, uint32_t b1)
{
    asm volatile(
        "mma.sync.aligned.m16n8k16.row.col.f32.f16.f16.f32 "
        "{%0,%1,%2,%3}, {%4,%5,%6,%7}, {%8,%9}, {%0,%1,%2,%3};\n"
        : "+f"(c0), "+f"(c1), "+f"(c2), "+f"(c3)
        : "r"(a0), "r"(a1), "r"(a2), "r"(a3), "r"(b0), "r"(b1));
}

__device__ __forceinline__ void cpa16(uint32_t dst, const void* src)
{
    asm volatile("cp.async.cg.shared.global [%0], [%1], 16;\n" :: "r"(dst), "l"(src));
}
__device__ __forceinline__ void cpa_commit()
{
    asm volatile("cp.async.commit_group;\n" ::: "memory");
}
__device__ __forceinline__ void cpa_wait0()
{
    asm volatile("cp.async.wait_group 0;\n" ::: "memory");
}

// ---------------------------------------------------------------------------
// Weight + bias convert.
// ---------------------------------------------------------------------------
__global__ void wconv_kernel(
    const float* __restrict__ Wq, const float* __restrict__ bq,
    const float* __restrict__ Wk, const float* __restrict__ bk,
    const float* __restrict__ Wv, const float* __restrict__ bv)
{
    const int gid = blockIdx.x * 256 + threadIdx.x;
    for (int i = gid; i < MROWS * CDIM; i += gridDim.x * 256) {
        const int row = i >> 8, col = i & 255;
        float v;
        if (row < 32)       v = Wq[row * CDIM + col];
        else if (row < 64)  v = Wk[(row - 32) * CDIM + col];
        else                v = Wv[(row - 64) * CDIM + col];
        g_Wh[i] = __float2half_rn(v);
    }
    if (gid < MROWS) {
        g_ball[gid] = (gid < 32) ? bq[gid] : (gid < 64) ? bk[gid - 32] : bv[gid - 64];
    }
}

// ---------------------------------------------------------------------------
// x transpose+convert: x [B][C][N] fp32 -> g_xhT [B][N][C] fp16.
// ---------------------------------------------------------------------------
__global__ __launch_bounds__(256) void xconv_kernel(const float* __restrict__ x)
{
    __shared__ __half ts[32 * 40];
    const int b  = blockIdx.z;
    const int c0 = blockIdx.y * 32;
    const int n0 = blockIdx.x * 32;
    const int tid = threadIdx.x;

#pragma unroll
    for (int it = 0; it < 4; it++) {
        const int idx = tid + 256 * it;
        const int cr = idx >> 5, nc = idx & 31;
        ts[nc * 40 + cr] =
            __float2half_rn(x[((size_t)b * CDIM + c0 + cr) * NPIX + n0 + nc]);
    }
    __syncthreads();
    if (tid < 128) {
        const int r = tid >> 2, sg = tid & 3;
        *(uint4*)&g_xhT[((size_t)b * NPIX + n0 + r) * CDIM + c0 + sg * 8] =
            *(const uint4*)&ts[r * 40 + sg * 8];
    }
}

// ---------------------------------------------------------------------------
// Projection GEMM (fp16 HMMA, fp32 acc). Q pre-scaled by log2(e).
// K and V^T outputs stored 32-wide k-PERMUTED (see top comment).
// ---------------------------------------------------------------------------
#define GP 72

__global__ __launch_bounds__(256, 2) void proj_gemm_kernel()
{
    __shared__ __align__(16) char smraw[(64 + 128) * GP * 2];
    __half* Wa = (__half*)smraw;
    __half* Xb = (__half*)(smraw + 64 * GP * 2);

    const int n0 = blockIdx.x * 128;
    const int b  = blockIdx.y;
    const int m0 = blockIdx.z * 64;
    const int tid = threadIdx.x;
    const int w = tid >> 5, lane = tid & 31;
    const int g = lane >> 2, t = lane & 3;
    const int mw = 32 * (w & 1);
    const int nw = 32 * (w >> 1);

    float acc[2][4][4];
#pragma unroll
    for (int i = 0; i < 2; i++)
#pragma unroll
        for (int j = 0; j < 4; j++)
#pragma unroll
            for (int k = 0; k < 4; k++) acc[i][j][k] = 0.f;

    for (int kc = 0; kc < 4; kc++) {
        __syncthreads();
#pragma unroll
        for (int r = 0; r < 2; r++) {
            const int idx = tid + 256 * r;
            const int row = idx >> 3, seg = idx & 7;
            *(uint4*)&Wa[row * GP + seg * 8] =
                *(const uint4*)&g_Wh[(m0 + row) * CDIM + kc * 64 + seg * 8];
        }
#pragma unroll
        for (int r = 0; r < 4; r++) {
            const int idx = tid + 256 * r;
            const int row = idx >> 3, seg = idx & 7;
            *(uint4*)&Xb[row * GP + seg * 8] =
                *(const uint4*)&g_xhT[((size_t)b * NPIX + n0 + row) * CDIM + kc * 64 + seg * 8];
        }
        __syncthreads();

#pragma unroll
        for (int s = 0; s < 4; s++) {
            uint32_t a[2][4];
#pragma unroll
            for (int i = 0; i < 2; i++) {
                const __half* base = &Wa[(mw + 16 * i + g) * GP + 2 * t + 16 * s];
                a[i][0] = *(const uint32_t*)base;
                a[i][2] = *(const uint32_t*)(base + 8);
                const __half* b8 = base + 8 * GP;
                a[i][1] = *(const uint32_t*)b8;
                a[i][3] = *(const uint32_t*)(b8 + 8);
            }
#pragma unroll
            for (int j = 0; j < 4; j++) {
                const __half* kb = &Xb[(nw + 8 * j + g) * GP + 2 * t + 16 * s];
                const uint32_t b0 = *(const uint32_t*)kb;
                const uint32_t b1 = *(const uint32_t*)(kb + 8);
                mma16816(acc[0][j][0], acc[0][j][1], acc[0][j][2], acc[0][j][3],
                         a[0][0], a[0][1], a[0][2], a[0][3], b0, b1);
                mma16816(acc[1][j][0], acc[1][j][1], acc[1][j][2], acc[1][j][3],
                         a[1][0], a[1][1], a[1][2], a[1][3], b0, b1);
            }
        }
    }

    if (m0 >= 64) {
        // ---- V epilogue: permuted store into g_VhT[c][perm32(n)] ----
#pragma unroll
        for (int i = 0; i < 2; i++) {
            const int r0 = mw + 16 * i + g;
            const int r1 = r0 + 8;
            const float bb0 = g_ball[m0 + r0];
            const float bb1 = g_ball[m0 + r1];
            const size_t c0g = (size_t)b * CDIM + (m0 - 64 + r0);
            const size_t c1g = (size_t)b * CDIM + (m0 - 64 + r1);
#pragma unroll
            for (int j = 0; j < 4; j++) {
                const int n = n0 + nw + 8 * j + 2 * t;
                const int np = perm32(n);
                *(__half2*)&g_VhT[c0g * NPIX + np] =
                    __floats2half2_rn(acc[i][j][0] + bb0, acc[i][j][1] + bb0);
                *(__half2*)&g_VhT[c1g * NPIX + np] =
                    __floats2half2_rn(acc[i][j][2] + bb1, acc[i][j][3] + bb1);
            }
        }
    } else {
        __half* Obuf = Xb;
        __syncthreads();
        // rows 0-31 = Q (scale by log2e), rows 32-63 = K (scale 1)
        const float qsc = (mw == 0) ? LOG2E : 1.0f;
#pragma unroll
        for (int i = 0; i < 2; i++) {
            const int r0 = mw + 16 * i + g;
            const int r1 = r0 + 8;
            const float bb0 = g_ball[r0];
            const float bb1 = g_ball[r1];
#pragma unroll
            for (int j = 0; j < 4; j++) {
                const int n = nw + 8 * j + 2 * t;
                Obuf[n * GP + r0]       = __float2half_rn((acc[i][j][0] + bb0) * qsc);
                Obuf[(n + 1) * GP + r0] = __float2half_rn((acc[i][j][1] + bb0) * qsc);
                Obuf[n * GP + r1]       = __float2half_rn((acc[i][j][2] + bb1) * qsc);
                Obuf[(n + 1) * GP + r1] = __float2half_rn((acc[i][j][3] + bb1) * qsc);
            }
        }
        __syncthreads();
#pragma unroll
        for (int r = 0; r < 2; r++) {
            const int idx = tid + 256 * r;
            const int n = idx >> 2, seg = idx & 3;
            // Q: unpermuted uint4 copy
            *(uint4*)&g_Qh[((size_t)b * NPIX + n0 + n) * CQK + seg * 8] =
                *(const uint4*)&Obuf[n * GP + seg * 8];
            // K: permuted pair stores (d along 32-dim)
#pragma unroll
            for (int pp = 0; pp < 4; pp++) {
                const int d = seg * 8 + pp * 2;
                *(__half2*)&g_Kh[((size_t)b * NPIX + n0 + n) * CQK + perm32(d)] =
                    *(const __half2*)&Obuf[n * GP + 32 + d];
            }
        }
    }
}

// ---------------------------------------------------------------------------
// Flash attention v9: static-max softmax; warp = 32 queries x 64 channels
// (two 16-row blocks sharing K and V fragment loads -> V smem traffic halved,
// one V LDS.128 feeds 4 MMAs). ones-MMA row sums; cp.async double-buffered.
// Warp w: query rows 32*(w&1).., channels 64*(w>>1)..
// ---------------------------------------------------------------------------
#define QTILE 64
#define KTILE 64
#define KP    32   // halves per K row (64B stride: LDS.128 conflict-free, no pad)
#define VP    96   // halves per V^T row (192B stride: LDS.128 conflict-free)
#define OFS_K0 0                       // 64*64   = 4096
#define OFS_K1 4096
#define OFS_V0 8192                    // 256*192 = 49152
#define OFS_V1 57344
#define ATT_SMEM 106496
#define OBP 66     // Obuf [256 c][66] floats (aliases buffers)

__global__ __launch_bounds__(256, 2) void attn_kernel(
    float* __restrict__ out, const float* __restrict__ gamma)
{
    extern __shared__ __align__(16) char sm[];
    const uint32_t smbase = (uint32_t)__cvta_generic_to_shared(sm);

    const int b   = blockIdx.y;
    const int q0  = blockIdx.x * QTILE;
    const int tid = threadIdx.x;
    const int w   = tid >> 5;
    const int lane = tid & 31;
    const int g = lane >> 2;
    const int t = lane & 3;

    const int qr = 32 * (w & 1);     // query row base (32 rows, 2 blocks of 16)
    const int ch = 64 * (w >> 1);    // channel slice base (64 channels)

    const size_t bN = (size_t)b * NPIX;
    const size_t bC = (size_t)b * CDIM;

    // ---- Q fragments for both 16-row blocks (pre-scaled by log2e) ----
    uint32_t qa[2][2][4];
#pragma unroll
    for (int blk = 0; blk < 2; blk++) {
        const __half* r0p = &g_Qh[(bN + q0 + qr + 16 * blk + g) * CQK];
        const __half* r8p = r0p + 8 * CQK;
#pragma unroll
        for (int s = 0; s < 2; s++) {
            qa[blk][s][0] = *(const uint32_t*)&r0p[16 * s + 2 * t];
            qa[blk][s][1] = *(const uint32_t*)&r8p[16 * s + 2 * t];
            qa[blk][s][2] = *(const uint32_t*)&r0p[16 * s + 8 + 2 * t];
            qa[blk][s][3] = *(const uint32_t*)&r8p[16 * s + 8 + 2 * t];
        }
    }

    float acc[2][8][4];
#pragma unroll
    for (int blk = 0; blk < 2; blk++)
#pragma unroll
        for (int j = 0; j < 8; j++)
#pragma unroll
            for (int k = 0; k < 4; k++) acc[blk][j][k] = 0.f;

    // row-sum accumulators per block (ones-MMA C fragments)
    float ao[2][4] = {{0.f, 0.f, 0.f, 0.f}, {0.f, 0.f, 0.f, 0.f}};

    // tile loader (cp.async, 16B chunks; gmem already permuted so copies are linear)
    const int krow = tid >> 2, kseg = tid & 3;
    auto issue_tile = [&](int buf, int m0g) {
        const uint32_t kb = smbase + (buf ? OFS_K1 : OFS_K0);
        const uint32_t vb = smbase + (buf ? OFS_V1 : OFS_V0);
        cpa16(kb + krow * (KP * 2) + kseg * 16,
              &g_Kh[(bN + m0g + krow) * CQK + kseg * 8]);
#pragma unroll
        for (int it = 0; it < 8; it++) {
            const int idx = tid + 256 * it;
            const int c = idx >> 3, seg = idx & 7;
            cpa16(vb + c * (VP * 2) + seg * 16,
                  &g_VhT[(bC + c) * NPIX + m0g + seg * 8]);
        }
        cpa_commit();
    };

    issue_tile(0, 0);

    for (int kt = 0; kt < NPIX / KTILE; kt++) {
        const int buf = kt & 1;
        cpa_wait0();
        __syncthreads();                       // tile ready; prev reads done
        if (kt + 1 < NPIX / KTILE)
            issue_tile(buf ^ 1, (kt + 1) * KTILE);

        const __half* Ks  = (const __half*)(sm + (buf ? OFS_K1 : OFS_K0));
        const __half* VsT = (const __half*)(sm + (buf ? OFS_V1 : OFS_V0));

        // ---- S = Q K^T for BOTH query blocks, sharing each K LDS.128;
        //      P = 2^S packed straight into fp16 A-fragments (no max shift) ----
        uint32_t pa[2][4][4];
#pragma unroll
        for (int s = 0; s < 4; s++) {
            float a00, a01, a02, a03, b00, b01, b02, b03;   // block 0
            float a10, a11, a12, a13, b10, b11, b12, b13;   // block 1
            {
                const uint4 kk = *(const uint4*)&Ks[(16 * s + g) * KP + 8 * t];
                float c0 = 0.f, c1 = 0.f, c2 = 0.f, c3 = 0.f;
                mma16816(c0, c1, c2, c3, qa[0][0][0], qa[0][0][1], qa[0][0][2], qa[0][0][3], kk.x, kk.y);
                mma16816(c0, c1, c2, c3, qa[0][1][0], qa[0][1][1], qa[0][1][2], qa[0][1][3], kk.z, kk.w);
                a00 = c0; a01 = c1; a02 = c2; a03 = c3;
                float d0 = 0.f, d1 = 0.f, d2 = 0.f, d3 = 0.f;
                mma16816(d0, d1, d2, d3, qa[1][0][0], qa[1][0][1], qa[1][0][2], qa[1][0][3], kk.x, kk.y);
                mma16816(d0, d1, d2, d3, qa[1][1][0], qa[1][1][1], qa[1][1][2], qa[1][1][3], kk.z, kk.w);
                a10 = d0; a11 = d1; a12 = d2; a13 = d3;
            }
            {
                const uint4 kk = *(const uint4*)&Ks[(16 * s + 8 + g) * KP + 8 * t];
                float c0 = 0.f, c1 = 0.f, c2 = 0.f, c3 = 0.f;
                mma16816(c0, c1, c2, c3, qa[0][0][0], qa[0][0][1], qa[0][0][2], qa[0][0][3], kk.x, kk.y);
                mma16816(c0, c1, c2, c3, qa[0][1][0], qa[0][1][1], qa[0][1][2], qa[0][1][3], kk.z, kk.w);
                b00 = c0; b01 = c1; b02 = c2; b03 = c3;
                float d0 = 0.f, d1 = 0.f, d2 = 0.f, d3 = 0.f;
                mma16816(d0, d1, d2, d3, qa[1][0][0], qa[1][0][1], qa[1][0][2], qa[1][0][3], kk.x, kk.y);
                mma16816(d0, d1, d2, d3, qa[1][1][0], qa[1][1][1], qa[1][1][2], qa[1][1][3], kk.z, kk.w);
                b10 = d0; b11 = d1; b12 = d2; b13 = d3;
            }
            pa[0][s][0] = ex2_h2(a00, a01);
            pa[0][s][1] = ex2_h2(a02, a03);
            pa[0][s][2] = ex2_h2(b00, b01);
            pa[0][s][3] = ex2_h2(b02, b03);
            pa[1][s][0] = ex2_h2(a10, a11);
            pa[1][s][1] = ex2_h2(a12, a13);
            pa[1][s][2] = ex2_h2(b10, b11);
            pa[1][s][3] = ex2_h2(b12, b13);
        }

        // ---- row sums via ones-MMA (per block) ----
#pragma unroll
        for (int s = 0; s < 4; s++) {
            mma16816(ao[0][0], ao[0][1], ao[0][2], ao[0][3],
                     pa[0][s][0], pa[0][s][1], pa[0][s][2], pa[0][s][3], ONES_H2, ONES_H2);
            mma16816(ao[1][0], ao[1][1], ao[1][2], ao[1][3],
                     pa[1][s][0], pa[1][s][1], pa[1][s][2], pa[1][s][3], ONES_H2, ONES_H2);
        }

        // ---- O += P V : one V LDS.128 feeds 4 MMAs (2 k-steps x 2 blocks) ----
#pragma unroll
        for (int sb = 0; sb < 2; sb++) {
#pragma unroll
            for (int jj = 0; jj < 8; jj++) {
                const uint4 vv =
                    *(const uint4*)&VsT[(ch + 8 * jj + g) * VP + 32 * sb + 8 * t];
                mma16816(acc[0][jj][0], acc[0][jj][1], acc[0][jj][2], acc[0][jj][3],
                         pa[0][2 * sb][0], pa[0][2 * sb][1], pa[0][2 * sb][2], pa[0][2 * sb][3],
                         vv.x, vv.y);
                mma16816(acc[0][jj][0], acc[0][jj][1], acc[0][jj][2], acc[0][jj][3],
                         pa[0][2 * sb + 1][0], pa[0][2 * sb + 1][1],
                         pa[0][2 * sb + 1][2], pa[0][2 * sb + 1][3],
                         vv.z, vv.w);
                mma16816(acc[1][jj][0], acc[1][jj][1], acc[1][jj][2], acc[1][jj][3],
                         pa[1][2 * sb][0], pa[1][2 * sb][1], pa[1][2 * sb][2], pa[1][2 * sb][3],
                         vv.x, vv.y);
                mma16816(acc[1][jj][0], acc[1][jj][1], acc[1][jj][2], acc[1][jj][3],
                         pa[1][2 * sb + 1][0], pa[1][2 * sb + 1][1],
                         pa[1][2 * sb + 1][2], pa[1][2 * sb + 1][3],
                         vv.z, vv.w);
            }
        }
    }

    // ---- epilogue: scale, transpose via smem, coalesced store ----
    const float gamma0 = gamma[0];

    float* Obuf = (float*)sm;   // [256 c][OBP]
    __syncthreads();            // everyone done reading V buffers
#pragma unroll
    for (int blk = 0; blk < 2; blk++) {
        const float inv0 = gamma0 / ao[blk][0];   // row qr+16blk+g
        const float inv1 = gamma0 / ao[blk][2];   // row qr+16blk+8+g
        const int r0 = qr + 16 * blk + g;
        const int r1 = r0 + 8;
#pragma unroll
        for (int jj = 0; jj < 8; jj++) {
            const int c = ch + 8 * jj + 2 * t;
            Obuf[c * OBP + r0]       = acc[blk][jj][0] * inv0;
            Obuf[(c + 1) * OBP + r0] = acc[blk][jj][1] * inv0;
            Obuf[c * OBP + r1]       = acc[blk][jj][2] * inv1;
            Obuf[(c + 1) * OBP + r1] = acc[blk][jj][3] * inv1;
        }
    }
    __syncthreads();
#pragma unroll
    for (int it = 0; it < 64; it++) {
        const int idx = tid + 256 * it;
        const int c = idx >> 6, q = idx & 63;
        out[(bC + c) * NPIX + q0 + q] = Obuf[c * OBP + q];
    }
}

// ---------------------------------------------------------------------------
// Inputs: x, Wq, bq, Wk, bk, Wv, bv, gamma. Output: float32 [B,C,H,W].
// ---------------------------------------------------------------------------
extern "C" void kernel_launch(void* const* d_in, const int* in_sizes, int n_in,
                              void* d_out, int out_size)
{
    const float* x     = (const float*)d_in[0];
    const float* Wq    = (const float*)d_in[1];
    const float* bq    = (const float*)d_in[2];
    const float* Wk    = (const float*)d_in[3];
    const float* bk    = (const float*)d_in[4];
    const float* Wv    = (const float*)d_in[5];
    const float* bv    = (const float*)d_in[6];
    const float* gamma = (const float*)d_in[7];
    float* out = (float*)d_out;

    cudaFuncSetAttribute(attn_kernel,
                         cudaFuncAttributeMaxDynamicSharedMemorySize, ATT_SMEM);

    wconv_kernel<<<80, 256>>>(Wq, bq, Wk, bk, Wv, bv);
    xconv_kernel<<<dim3(NPIX / 32, CDIM / 32, BATCH), 256>>>(x);
    proj_gemm_kernel<<<dim3(NPIX / 128, BATCH, 5), 256>>>();
    attn_kernel<<<dim3(NPIX / QTILE, BATCH), 256, ATT_SMEM>>>(out, gamma);
}

// round 15
// speedup vs baseline: 1.1098x; 1.1098x over previous
#include <cuda_runtime.h>
#include <cuda_fp16.h>
#include <cuda_bf16.h>
#include <math.h>
#include <stdint.h>

#define BATCH 4
#define CDIM  256
#define CQK   32
#define NPIX  4096   // 64*64
#define MROWS 320    // 32 (Q) + 32 (K) + 256 (V)
#define LOG2E 1.4426950408889634f
#define ONES_H2 0x3C003C00u   // half2(1.0, 1.0)

// fp16 scratch (static device globals: allowed)
// g_Kh / g_VhT stored 32-wide K-PERMUTED along the contraction dim: within
// each 32-element block, pair p (elements 2p,2p+1) sits at half-offset
// (p&3)*8 + (p>>2)*2. A thread's uint4 at halves 8t..8t+7 then holds
// (b0,b1) for TWO consecutive k-steps -> one LDS.128 feeds 2 MMAs.
__device__ __half g_Qh[BATCH * NPIX * CQK];    // Q pre-scaled by log2(e); UNPERMUTED
__device__ __half g_Kh[BATCH * NPIX * CQK];    // permuted along d (32)
__device__ __half g_VhT[(size_t)BATCH * CDIM * NPIX];   // [B][C][N], permuted along N 32-blocks
__device__ __half g_xhT[(size_t)BATCH * NPIX * CDIM];   // [B][N][C]
__device__ __half g_Wh[MROWS * CDIM];                   // Wq|Wk|Wv stacked
__device__ float  g_ball[MROWS];

// ---------------------------------------------------------------------------
// helpers (defined BEFORE all uses)
// ---------------------------------------------------------------------------
__device__ __forceinline__ int perm32(int n)   // n even; 32-wide permuted position
{
    const int p = (n >> 1) & 15;
    return (n & ~31) + (p & 3) * 8 + (p >> 2) * 2;
}

// pack (lo, hi) fp32 -> half2, then 2^x elementwise. Returns half2 bits.
__device__ __forceinline__ uint32_t ex2_h2(float lo, float hi)
{
    uint32_t h;
    asm("cvt.rn.f16x2.f32 %0, %1, %2;" : "=r"(h) : "f"(hi), "f"(lo));
    asm("ex2.approx.f16x2 %0, %0;" : "+r"(h));
    return h;
}

__device__ __forceinline__ void mma16816(
    float& c0, float& c1, float& c2, float& c3,
    uint32_t a0, uint32_t a1, uint32_t a2, uint32_t a3,
    uint32_t b0, uint32_t b1)
{
    asm volatile(
        "mma.sync.aligned.m16n8k16.row.col.f32.f16.f16.f32 "
        "{%0,%1,%2,%3}, {%4,%5,%6,%7}, {%8,%9}, {%0,%1,%2,%3};\n"
        : "+f"(c0), "+f"(c1), "+f"(c2), "+f"(c3)
        : "r"(a0), "r"(a1), "r"(a2), "r"(a3), "r"(b0), "r"(b1));
}

__device__ __forceinline__ void cpa16(uint32_t dst, const void* src)
{
    asm volatile("cp.async.cg.shared.global [%0], [%1], 16;\n" :: "r"(dst), "l"(src));
}
__device__ __forceinline__ void cpa_commit()
{
    asm volatile("cp.async.commit_group;\n" ::: "memory");
}
__device__ __forceinline__ void cpa_wait0()
{
    asm volatile("cp.async.wait_group 0;\n" ::: "memory");
}

// ---------------------------------------------------------------------------
// Fused prep kernel: x transpose+convert (all CTAs) + weight/bias convert
// (first 80 CTAs of the y=0,z=0 slice). Saves one launch.
// ---------------------------------------------------------------------------
__global__ __launch_bounds__(256) void prep_kernel(
    const float* __restrict__ x,
    const float* __restrict__ Wq, const float* __restrict__ bq,
    const float* __restrict__ Wk, const float* __restrict__ bk,
    const float* __restrict__ Wv, const float* __restrict__ bv)
{
    const int tid = threadIdx.x;

    // ---- weight convert (80 CTAs x 256 thr = 20480 iter-slots; 81920/4) ----
    if (blockIdx.y == 0 && blockIdx.z == 0 && blockIdx.x < 80) {
        const int base = blockIdx.x * 256 + tid;
#pragma unroll
        for (int r = 0; r < 4; r++) {
            const int i = base + 20480 * r;
            const int row = i >> 8, col = i & 255;
            float v;
            if (row < 32)       v = Wq[row * CDIM + col];
            else if (row < 64)  v = Wk[(row - 32) * CDIM + col];
            else                v = Wv[(row - 64) * CDIM + col];
            g_Wh[i] = __float2half_rn(v);
        }
        if (base < MROWS) {
            g_ball[base] = (base < 32) ? bq[base]
                         : (base < 64) ? bk[base - 32] : bv[base - 64];
        }
    }

    // ---- x transpose+convert tile ----
    __shared__ __half ts[32 * 40];
    const int b  = blockIdx.z;
    const int c0 = blockIdx.y * 32;
    const int n0 = blockIdx.x * 32;

#pragma unroll
    for (int it = 0; it < 4; it++) {
        const int idx = tid + 256 * it;
        const int cr = idx >> 5, nc = idx & 31;
        ts[nc * 40 + cr] =
            __float2half_rn(x[((size_t)b * CDIM + c0 + cr) * NPIX + n0 + nc]);
    }
    __syncthreads();
    if (tid < 128) {
        const int r = tid >> 2, sg = tid & 3;
        *(uint4*)&g_xhT[((size_t)b * NPIX + n0 + r) * CDIM + c0 + sg * 8] =
            *(const uint4*)&ts[r * 40 + sg * 8];
    }
}

// ---------------------------------------------------------------------------
// Projection GEMM (fp16 HMMA, fp32 acc). Q pre-scaled by log2(e).
// K and V^T outputs stored 32-wide k-PERMUTED (see top comment).
// ---------------------------------------------------------------------------
#define GP 72

__global__ __launch_bounds__(256, 2) void proj_gemm_kernel()
{
    __shared__ __align__(16) char smraw[(64 + 128) * GP * 2];
    __half* Wa = (__half*)smraw;
    __half* Xb = (__half*)(smraw + 64 * GP * 2);

    const int n0 = blockIdx.x * 128;
    const int b  = blockIdx.y;
    const int m0 = blockIdx.z * 64;
    const int tid = threadIdx.x;
    const int w = tid >> 5, lane = tid & 31;
    const int g = lane >> 2, t = lane & 3;
    const int mw = 32 * (w & 1);
    const int nw = 32 * (w >> 1);

    float acc[2][4][4];
#pragma unroll
    for (int i = 0; i < 2; i++)
#pragma unroll
        for (int j = 0; j < 4; j++)
#pragma unroll
            for (int k = 0; k < 4; k++) acc[i][j][k] = 0.f;

    for (int kc = 0; kc < 4; kc++) {
        __syncthreads();
#pragma unroll
        for (int r = 0; r < 2; r++) {
            const int idx = tid + 256 * r;
            const int row = idx >> 3, seg = idx & 7;
            *(uint4*)&Wa[row * GP + seg * 8] =
                *(const uint4*)&g_Wh[(m0 + row) * CDIM + kc * 64 + seg * 8];
        }
#pragma unroll
        for (int r = 0; r < 4; r++) {
            const int idx = tid + 256 * r;
            const int row = idx >> 3, seg = idx & 7;
            *(uint4*)&Xb[row * GP + seg * 8] =
                *(const uint4*)&g_xhT[((size_t)b * NPIX + n0 + row) * CDIM + kc * 64 + seg * 8];
        }
        __syncthreads();

#pragma unroll
        for (int s = 0; s < 4; s++) {
            uint32_t a[2][4];
#pragma unroll
            for (int i = 0; i < 2; i++) {
                const __half* base = &Wa[(mw + 16 * i + g) * GP + 2 * t + 16 * s];
                a[i][0] = *(const uint32_t*)base;
                a[i][2] = *(const uint32_t*)(base + 8);
                const __half* b8 = base + 8 * GP;
                a[i][1] = *(const uint32_t*)b8;
                a[i][3] = *(const uint32_t*)(b8 + 8);
            }
#pragma unroll
            for (int j = 0; j < 4; j++) {
                const __half* kb = &Xb[(nw + 8 * j + g) * GP + 2 * t + 16 * s];
                const uint32_t b0 = *(const uint32_t*)kb;
                const uint32_t b1 = *(const uint32_t*)(kb + 8);
                mma16816(acc[0][j][0], acc[0][j][1], acc[0][j][2], acc[0][j][3],
                         a[0][0], a[0][1], a[0][2], a[0][3], b0, b1);
                mma16816(acc[1][j][0], acc[1][j][1], acc[1][j][2], acc[1][j][3],
                         a[1][0], a[1][1], a[1][2], a[1][3], b0, b1);
            }
        }
    }

    if (m0 >= 64) {
        // ---- V epilogue: permuted store into g_VhT[c][perm32(n)] ----
#pragma unroll
        for (int i = 0; i < 2; i++) {
            const int r0 = mw + 16 * i + g;
            const int r1 = r0 + 8;
            const float bb0 = g_ball[m0 + r0];
            const float bb1 = g_ball[m0 + r1];
            const size_t c0g = (size_t)b * CDIM + (m0 - 64 + r0);
            const size_t c1g = (size_t)b * CDIM + (m0 - 64 + r1);
#pragma unroll
            for (int j = 0; j < 4; j++) {
                const int n = n0 + nw + 8 * j + 2 * t;
                const int np = perm32(n);
                *(__half2*)&g_VhT[c0g * NPIX + np] =
                    __floats2half2_rn(acc[i][j][0] + bb0, acc[i][j][1] + bb0);
                *(__half2*)&g_VhT[c1g * NPIX + np] =
                    __floats2half2_rn(acc[i][j][2] + bb1, acc[i][j][3] + bb1);
            }
        }
    } else {
        __half* Obuf = Xb;
        __syncthreads();
        // rows 0-31 = Q (scale by log2e), rows 32-63 = K (scale 1)
        const float qsc = (mw == 0) ? LOG2E : 1.0f;
#pragma unroll
        for (int i = 0; i < 2; i++) {
            const int r0 = mw + 16 * i + g;
            const int r1 = r0 + 8;
            const float bb0 = g_ball[r0];
            const float bb1 = g_ball[r1];
#pragma unroll
            for (int j = 0; j < 4; j++) {
                const int n = nw + 8 * j + 2 * t;
                Obuf[n * GP + r0]       = __float2half_rn((acc[i][j][0] + bb0) * qsc);
                Obuf[(n + 1) * GP + r0] = __float2half_rn((acc[i][j][1] + bb0) * qsc);
                Obuf[n * GP + r1]       = __float2half_rn((acc[i][j][2] + bb1) * qsc);
                Obuf[(n + 1) * GP + r1] = __float2half_rn((acc[i][j][3] + bb1) * qsc);
            }
        }
        __syncthreads();
#pragma unroll
        for (int r = 0; r < 2; r++) {
            const int idx = tid + 256 * r;
            const int n = idx >> 2, seg = idx & 3;
            // Q: unpermuted uint4 copy
            *(uint4*)&g_Qh[((size_t)b * NPIX + n0 + n) * CQK + seg * 8] =
                *(const uint4*)&Obuf[n * GP + seg * 8];
            // K: permuted pair stores (d along 32-dim)
#pragma unroll
            for (int pp = 0; pp < 4; pp++) {
                const int d = seg * 8 + pp * 2;
                *(__half2*)&g_Kh[((size_t)b * NPIX + n0 + n) * CQK + perm32(d)] =
                    *(const __half2*)&Obuf[n * GP + 32 + d];
            }
        }
    }
}

// ---------------------------------------------------------------------------
// Flash attention v10 (= R13 structure, split-s scheduling): static-max
// softmax; warp = 16 queries x 128 channels (V x4 / QK x2 Pareto point);
// inner loop: QK(s0,1)+ex2 -> QK(s2,3 raw) -> PV(sb0) -> ex2(s2,3) -> ones
// -> PV(sb1), so the second ex2/cvt chain hides under PV MMAs and peak live
// S registers halve. LDS.128 B-fragments (32-wide permuted K/V);
// cp.async double-buffered. Warp w: rows 16*(w&3).., channels 128*(w>>2)..
// ---------------------------------------------------------------------------
#define QTILE 64
#define KTILE 64
#define KP    32   // halves per K row (64B stride: LDS.128 conflict-free, no pad)
#define VP    96   // halves per V^T row (192B stride: LDS.128 conflict-free)
#define OFS_K0 0                       // 64*64   = 4096
#define OFS_K1 4096
#define OFS_V0 8192                    // 256*192 = 49152
#define OFS_V1 57344
#define ATT_SMEM 106496
#define OBP 66     // Obuf [256 c][66] floats (aliases buffers)

__global__ __launch_bounds__(256, 2) void attn_kernel(
    float* __restrict__ out, const float* __restrict__ gamma)
{
    extern __shared__ __align__(16) char sm[];
    const uint32_t smbase = (uint32_t)__cvta_generic_to_shared(sm);

    const int b   = blockIdx.y;
    const int q0  = blockIdx.x * QTILE;
    const int tid = threadIdx.x;
    const int w   = tid >> 5;
    const int lane = tid & 31;
    const int g = lane >> 2;
    const int t = lane & 3;

    const int qr = 16 * (w & 3);     // query row base for this warp
    const int ch = 128 * (w >> 2);   // channel half base

    const size_t bN = (size_t)b * NPIX;
    const size_t bC = (size_t)b * CDIM;

    // ---- Q fragments straight from global (one time; pre-scaled by log2e) ----
    uint32_t qa[2][4];
    {
        const __half* r0p = &g_Qh[(bN + q0 + qr + g) * CQK];
        const __half* r8p = r0p + 8 * CQK;
#pragma unroll
        for (int s = 0; s < 2; s++) {
            qa[s][0] = *(const uint32_t*)&r0p[16 * s + 2 * t];
            qa[s][1] = *(const uint32_t*)&r8p[16 * s + 2 * t];
            qa[s][2] = *(const uint32_t*)&r0p[16 * s + 8 + 2 * t];
            qa[s][3] = *(const uint32_t*)&r8p[16 * s + 8 + 2 * t];
        }
    }

    float acc[16][4];
#pragma unroll
    for (int j = 0; j < 16; j++)
#pragma unroll
        for (int k = 0; k < 4; k++) acc[j][k] = 0.f;

    // l carried as ones-MMA accumulators: ao0/ao1 -> row qr+g, ao2/ao3 -> row qr+8+g
    float ao0 = 0.f, ao1 = 0.f, ao2 = 0.f, ao3 = 0.f;

    // tile loader (cp.async, 16B chunks; gmem already permuted so copies are linear)
    const int krow = tid >> 2, kseg = tid & 3;
    auto issue_tile = [&](int buf, int m0g) {
        const uint32_t kb = smbase + (buf ? OFS_K1 : OFS_K0);
        const uint32_t vb = smbase + (buf ? OFS_V1 : OFS_V0);
        cpa16(kb + krow * (KP * 2) + kseg * 16,
              &g_Kh[(bN + m0g + krow) * CQK + kseg * 8]);
#pragma unroll
        for (int it = 0; it < 8; it++) {
            const int idx = tid + 256 * it;
            const int c = idx >> 3, seg = idx & 7;
            cpa16(vb + c * (VP * 2) + seg * 16,
                  &g_VhT[(bC + c) * NPIX + m0g + seg * 8]);
        }
        cpa_commit();
    };

    issue_tile(0, 0);

    for (int kt = 0; kt < NPIX / KTILE; kt++) {
        const int buf = kt & 1;
        cpa_wait0();
        __syncthreads();                       // tile ready; prev reads done
        if (kt + 1 < NPIX / KTILE)
            issue_tile(buf ^ 1, (kt + 1) * KTILE);

        const __half* Ks  = (const __half*)(sm + (buf ? OFS_K1 : OFS_K0));
        const __half* VsT = (const __half*)(sm + (buf ? OFS_V1 : OFS_V0));

        uint32_t pa[4][4];

        // ---- QK s=0,1 with immediate ex2 -> pa[0],pa[1] ----
#pragma unroll
        for (int s = 0; s < 2; s++) {
            float a0, a1, a2, a3, e0, e1, e2, e3;
            {
                const uint4 kk = *(const uint4*)&Ks[(16 * s + g) * KP + 8 * t];
                float c0 = 0.f, c1 = 0.f, c2 = 0.f, c3 = 0.f;
                mma16816(c0, c1, c2, c3, qa[0][0], qa[0][1], qa[0][2], qa[0][3], kk.x, kk.y);
                mma16816(c0, c1, c2, c3, qa[1][0], qa[1][1], qa[1][2], qa[1][3], kk.z, kk.w);
                a0 = c0; a1 = c1; a2 = c2; a3 = c3;
            }
            {
                const uint4 kk = *(const uint4*)&Ks[(16 * s + 8 + g) * KP + 8 * t];
                float c0 = 0.f, c1 = 0.f, c2 = 0.f, c3 = 0.f;
                mma16816(c0, c1, c2, c3, qa[0][0], qa[0][1], qa[0][2], qa[0][3], kk.x, kk.y);
                mma16816(c0, c1, c2, c3, qa[1][0], qa[1][1], qa[1][2], qa[1][3], kk.z, kk.w);
                e0 = c0; e1 = c1; e2 = c2; e3 = c3;
            }
            pa[s][0] = ex2_h2(a0, a1);
            pa[s][1] = ex2_h2(a2, a3);
            pa[s][2] = ex2_h2(e0, e1);
            pa[s][3] = ex2_h2(e2, e3);
        }

        // ---- QK s=2,3 raw scores (ex2 deferred past PV sb=0) ----
        float sc2[2][8];
#pragma unroll
        for (int s = 0; s < 2; s++) {
            {
                const uint4 kk = *(const uint4*)&Ks[(16 * (s + 2) + g) * KP + 8 * t];
                float c0 = 0.f, c1 = 0.f, c2 = 0.f, c3 = 0.f;
                mma16816(c0, c1, c2, c3, qa[0][0], qa[0][1], qa[0][2], qa[0][3], kk.x, kk.y);
                mma16816(c0, c1, c2, c3, qa[1][0], qa[1][1], qa[1][2], qa[1][3], kk.z, kk.w);
                sc2[s][0] = c0; sc2[s][1] = c1; sc2[s][2] = c2; sc2[s][3] = c3;
            }
            {
                const uint4 kk = *(const uint4*)&Ks[(16 * (s + 2) + 8 + g) * KP + 8 * t];
                float c0 = 0.f, c1 = 0.f, c2 = 0.f, c3 = 0.f;
                mma16816(c0, c1, c2, c3, qa[0][0], qa[0][1], qa[0][2], qa[0][3], kk.x, kk.y);
                mma16816(c0, c1, c2, c3, qa[1][0], qa[1][1], qa[1][2], qa[1][3], kk.z, kk.w);
                sc2[s][4] = c0; sc2[s][5] = c1; sc2[s][6] = c2; sc2[s][7] = c3;
            }
        }

        // ---- PV sb=0 (uses pa[0],pa[1]; overlaps the deferred ex2 below) ----
#pragma unroll
        for (int jj = 0; jj < 16; jj++) {
            const uint4 vv = *(const uint4*)&VsT[(ch + 8 * jj + g) * VP + 8 * t];
            mma16816(acc[jj][0], acc[jj][1], acc[jj][2], acc[jj][3],
                     pa[0][0], pa[0][1], pa[0][2], pa[0][3], vv.x, vv.y);
            mma16816(acc[jj][0], acc[jj][1], acc[jj][2], acc[jj][3],
                     pa[1][0], pa[1][1], pa[1][2], pa[1][3], vv.z, vv.w);
        }

        // ---- deferred ex2 for s=2,3 -> pa[2],pa[3] ----
#pragma unroll
        for (int s = 0; s < 2; s++) {
            pa[2 + s][0] = ex2_h2(sc2[s][0], sc2[s][1]);
            pa[2 + s][1] = ex2_h2(sc2[s][2], sc2[s][3]);
            pa[2 + s][2] = ex2_h2(sc2[s][4], sc2[s][5]);
            pa[2 + s][3] = ex2_h2(sc2[s][6], sc2[s][7]);
        }

        // ---- row sums via ones-MMA ----
#pragma unroll
        for (int s = 0; s < 4; s++)
            mma16816(ao0, ao1, ao2, ao3,
                     pa[s][0], pa[s][1], pa[s][2], pa[s][3], ONES_H2, ONES_H2);

        // ---- PV sb=1 (uses pa[2],pa[3]) ----
#pragma unroll
        for (int jj = 0; jj < 16; jj++) {
            const uint4 vv = *(const uint4*)&VsT[(ch + 8 * jj + g) * VP + 32 + 8 * t];
            mma16816(acc[jj][0], acc[jj][1], acc[jj][2], acc[jj][3],
                     pa[2][0], pa[2][1], pa[2][2], pa[2][3], vv.x, vv.y);
            mma16816(acc[jj][0], acc[jj][1], acc[jj][2], acc[jj][3],
                     pa[3][0], pa[3][1], pa[3][2], pa[3][3], vv.z, vv.w);
        }
    }

    // ---- epilogue: scale, transpose via smem, coalesced store ----
    const float gamma0 = gamma[0];
    const float inv0 = gamma0 / ao0;   // row qr+g
    const float inv1 = gamma0 / ao2;   // row qr+8+g

    float* Obuf = (float*)sm;   // [256 c][OBP]
    __syncthreads();            // everyone done reading V buffers
#pragma unroll
    for (int jj = 0; jj < 16; jj++) {
        const int c = ch + 8 * jj + 2 * t;
        const int r0 = qr + g;
        const int r1 = r0 + 8;
        Obuf[c * OBP + r0]       = acc[jj][0] * inv0;
        Obuf[(c + 1) * OBP + r0] = acc[jj][1] * inv0;
        Obuf[c * OBP + r1]       = acc[jj][2] * inv1;
        Obuf[(c + 1) * OBP + r1] = acc[jj][3] * inv1;
    }
    __syncthreads();
#pragma unroll
    for (int it = 0; it < 64; it++) {
        const int idx = tid + 256 * it;
        const int c = idx >> 6, q = idx & 63;
        out[(bC + c) * NPIX + q0 + q] = Obuf[c * OBP + q];
    }
}

// ---------------------------------------------------------------------------
// Inputs: x, Wq, bq, Wk, bk, Wv, bv, gamma. Output: float32 [B,C,H,W].
// ---------------------------------------------------------------------------
extern "C" void kernel_launch(void* const* d_in, const int* in_sizes, int n_in,
                              void* d_out, int out_size)
{
    const float* x     = (const float*)d_in[0];
    const float* Wq    = (const float*)d_in[1];
    const float* bq    = (const float*)d_in[2];
    const float* Wk    = (const float*)d_in[3];
    const float* bk    = (const float*)d_in[4];
    const float* Wv    = (const float*)d_in[5];
    const float* bv    = (const float*)d_in[6];
    const float* gamma = (const float*)d_in[7];
    float* out = (float*)d_out;

    cudaFuncSetAttribute(attn_kernel,
                         cudaFuncAttributeMaxDynamicSharedMemorySize, ATT_SMEM);

    prep_kernel<<<dim3(NPIX / 32, CDIM / 32, BATCH), 256>>>(x, Wq, bq, Wk, bk, Wv, bv);
    proj_gemm_kernel<<<dim3(NPIX / 128, BATCH, 5), 256>>>();
    attn_kernel<<<dim3(NPIX / QTILE, BATCH), 256, ATT_SMEM>>>(out, gamma);
}

// round 17
// speedup vs baseline: 1.1366x; 1.0241x over previous
#include <cuda_runtime.h>
#include <cuda_fp16.h>
#include <cuda_bf16.h>
#include <math.h>
#include <stdint.h>

#define BATCH 4
#define CDIM  256
#define CQK   32
#define NPIX  4096   // 64*64
#define MROWS 320    // 32 (Q) + 32 (K) + 256 (V)
#define LOG2E 1.4426950408889634f
#define ONES_H2 0x3C003C00u   // half2(1.0, 1.0)

// fp16 scratch (static device globals: allowed)
// g_Kh / g_VhT stored 32-wide K-PERMUTED along the contraction dim: within
// each 32-element block, pair p (elements 2p,2p+1) sits at half-offset
// (p&3)*8 + (p>>2)*2. A thread's uint4 at halves 8t..8t+7 then holds
// (b0,b1) for TWO consecutive k-steps -> one LDS.128 feeds 2 MMAs.
__device__ __half g_Qh[BATCH * NPIX * CQK];    // Q pre-scaled by log2(e); UNPERMUTED
__device__ __half g_Kh[BATCH * NPIX * CQK];    // permuted along d (32)
__device__ __half g_VhT[(size_t)BATCH * CDIM * NPIX];   // [B][C][N], permuted along N 32-blocks
__device__ __half g_xhT[(size_t)BATCH * NPIX * CDIM];   // [B][N][C]
__device__ __half g_Wh[MROWS * CDIM];                   // Wq|Wk|Wv stacked
__device__ float  g_ball[MROWS];

// ---------------------------------------------------------------------------
// helpers (defined BEFORE all uses)
// ---------------------------------------------------------------------------
__device__ __forceinline__ int perm32(int n)   // n even; 32-wide permuted position
{
    const int p = (n >> 1) & 15;
    return (n & ~31) + (p & 3) * 8 + (p >> 2) * 2;
}

// pack (lo, hi) fp32 -> half2, then 2^x elementwise. Returns half2 bits.
__device__ __forceinline__ uint32_t ex2_h2(float lo, float hi)
{
    uint32_t h;
    asm("cvt.rn.f16x2.f32 %0, %1, %2;" : "=r"(h) : "f"(hi), "f"(lo));
    asm("ex2.approx.f16x2 %0, %0;" : "+r"(h));
    return h;
}

__device__ __forceinline__ void mma16816(
    float& c0, float& c1, float& c2, float& c3,
    uint32_t a0, uint32_t a1, uint32_t a2, uint32_t a3,
    uint32_t b0, uint32_t b1)
{
    asm volatile(
        "mma.sync.aligned.m16n8k16.row.col.f32.f16.f16.f32 "
        "{%0,%1,%2,%3}, {%4,%5,%6,%7}, {%8,%9}, {%0,%1,%2,%3};\n"
        : "+f"(c0), "+f"(c1), "+f"(c2), "+f"(c3)
        : "r"(a0), "r"(a1), "r"(a2), "r"(a3), "r"(b0), "r"(b1));
}

__device__ __forceinline__ void cpa16(uint32_t dst, const void* src)
{
    asm volatile("cp.async.cg.shared.global [%0], [%1], 16;\n" :: "r"(dst), "l"(src));
}
__device__ __forceinline__ void cpa_commit()
{
    asm volatile("cp.async.commit_group;\n" ::: "memory");
}
__device__ __forceinline__ void cpa_wait0()
{
    asm volatile("cp.async.wait_group 0;\n" ::: "memory");
}

// ---------------------------------------------------------------------------
// Fused prep kernel: x transpose+convert (all CTAs) + weight/bias convert
// (first 80 CTAs of the y=0,z=0 slice). Saves one launch.
// ---------------------------------------------------------------------------
__global__ __launch_bounds__(256) void prep_kernel(
    const float* __restrict__ x,
    const float* __restrict__ Wq, const float* __restrict__ bq,
    const float* __restrict__ Wk, const float* __restrict__ bk,
    const float* __restrict__ Wv, const float* __restrict__ bv)
{
    const int tid = threadIdx.x;

    // ---- weight convert (80 CTAs x 256 thr = 20480 iter-slots; 81920/4) ----
    if (blockIdx.y == 0 && blockIdx.z == 0 && blockIdx.x < 80) {
        const int base = blockIdx.x * 256 + tid;
#pragma unroll
        for (int r = 0; r < 4; r++) {
            const int i = base + 20480 * r;
            const int row = i >> 8, col = i & 255;
            float v;
            if (row < 32)       v = Wq[row * CDIM + col];
            else if (row < 64)  v = Wk[(row - 32) * CDIM + col];
            else                v = Wv[(row - 64) * CDIM + col];
            g_Wh[i] = __float2half_rn(v);
        }
        if (base < MROWS) {
            g_ball[base] = (base < 32) ? bq[base]
                         : (base < 64) ? bk[base - 32] : bv[base - 64];
        }
    }

    // ---- x transpose+convert tile ----
    __shared__ __half ts[32 * 40];
    const int b  = blockIdx.z;
    const int c0 = blockIdx.y * 32;
    const int n0 = blockIdx.x * 32;

#pragma unroll
    for (int it = 0; it < 4; it++) {
        const int idx = tid + 256 * it;
        const int cr = idx >> 5, nc = idx & 31;
        ts[nc * 40 + cr] =
            __float2half_rn(x[((size_t)b * CDIM + c0 + cr) * NPIX + n0 + nc]);
    }
    __syncthreads();
    if (tid < 128) {
        const int r = tid >> 2, sg = tid & 3;
        *(uint4*)&g_xhT[((size_t)b * NPIX + n0 + r) * CDIM + c0 + sg * 8] =
            *(const uint4*)&ts[r * 40 + sg * 8];
    }
}

// ---------------------------------------------------------------------------
// Projection GEMM (fp16 HMMA, fp32 acc). Q pre-scaled by log2(e).
// K and V^T outputs stored 32-wide k-PERMUTED (see top comment).
// ---------------------------------------------------------------------------
#define GP 72

__global__ __launch_bounds__(256, 2) void proj_gemm_kernel()
{
    __shared__ __align__(16) char smraw[(64 + 128) * GP * 2];
    __half* Wa = (__half*)smraw;
    __half* Xb = (__half*)(smraw + 64 * GP * 2);

    const int n0 = blockIdx.x * 128;
    const int b  = blockIdx.y;
    const int m0 = blockIdx.z * 64;
    const int tid = threadIdx.x;
    const int w = tid >> 5, lane = tid & 31;
    const int g = lane >> 2, t = lane & 3;
    const int mw = 32 * (w & 1);
    const int nw = 32 * (w >> 1);

    float acc[2][4][4];
#pragma unroll
    for (int i = 0; i < 2; i++)
#pragma unroll
        for (int j = 0; j < 4; j++)
#pragma unroll
            for (int k = 0; k < 4; k++) acc[i][j][k] = 0.f;

    for (int kc = 0; kc < 4; kc++) {
        __syncthreads();
#pragma unroll
        for (int r = 0; r < 2; r++) {
            const int idx = tid + 256 * r;
            const int row = idx >> 3, seg = idx & 7;
            *(uint4*)&Wa[row * GP + seg * 8] =
                *(const uint4*)&g_Wh[(m0 + row) * CDIM + kc * 64 + seg * 8];
        }
#pragma unroll
        for (int r = 0; r < 4; r++) {
            const int idx = tid + 256 * r;
            const int row = idx >> 3, seg = idx & 7;
            *(uint4*)&Xb[row * GP + seg * 8] =
                *(const uint4*)&g_xhT[((size_t)b * NPIX + n0 + row) * CDIM + kc * 64 + seg * 8];
        }
        __syncthreads();

#pragma unroll
        for (int s = 0; s < 4; s++) {
            uint32_t a[2][4];
#pragma unroll
            for (int i = 0; i < 2; i++) {
                const __half* base = &Wa[(mw + 16 * i + g) * GP + 2 * t + 16 * s];
                a[i][0] = *(const uint32_t*)base;
                a[i][2] = *(const uint32_t*)(base + 8);
                const __half* b8 = base + 8 * GP;
                a[i][1] = *(const uint32_t*)b8;
                a[i][3] = *(const uint32_t*)(b8 + 8);
            }
#pragma unroll
            for (int j = 0; j < 4; j++) {
                const __half* kb = &Xb[(nw + 8 * j + g) * GP + 2 * t + 16 * s];
                const uint32_t b0 = *(const uint32_t*)kb;
                const uint32_t b1 = *(const uint32_t*)(kb + 8);
                mma16816(acc[0][j][0], acc[0][j][1], acc[0][j][2], acc[0][j][3],
                         a[0][0], a[0][1], a[0][2], a[0][3], b0, b1);
                mma16816(acc[1][j][0], acc[1][j][1], acc[1][j][2], acc[1][j][3],
                         a[1][0], a[1][1], a[1][2], a[1][3], b0, b1);
            }
        }
    }

    if (m0 >= 64) {
        // ---- V epilogue: permuted store into g_VhT[c][perm32(n)] ----
#pragma unroll
        for (int i = 0; i < 2; i++) {
            const int r0 = mw + 16 * i + g;
            const int r1 = r0 + 8;
            const float bb0 = g_ball[m0 + r0];
            const float bb1 = g_ball[m0 + r1];
            const size_t c0g = (size_t)b * CDIM + (m0 - 64 + r0);
            const size_t c1g = (size_t)b * CDIM + (m0 - 64 + r1);
#pragma unroll
            for (int j = 0; j < 4; j++) {
                const int n = n0 + nw + 8 * j + 2 * t;
                const int np = perm32(n);
                *(__half2*)&g_VhT[c0g * NPIX + np] =
                    __floats2half2_rn(acc[i][j][0] + bb0, acc[i][j][1] + bb0);
                *(__half2*)&g_VhT[c1g * NPIX + np] =
                    __floats2half2_rn(acc[i][j][2] + bb1, acc[i][j][3] + bb1);
            }
        }
    } else {
        __half* Obuf = Xb;
        __syncthreads();
        // rows 0-31 = Q (scale by log2e), rows 32-63 = K (scale 1)
        const float qsc = (mw == 0) ? LOG2E : 1.0f;
#pragma unroll
        for (int i = 0; i < 2; i++) {
            const int r0 = mw + 16 * i + g;
            const int r1 = r0 + 8;
            const float bb0 = g_ball[r0];
            const float bb1 = g_ball[r1];
#pragma unroll
            for (int j = 0; j < 4; j++) {
                const int n = nw + 8 * j + 2 * t;
                Obuf[n * GP + r0]       = __float2half_rn((acc[i][j][0] + bb0) * qsc);
                Obuf[(n + 1) * GP + r0] = __float2half_rn((acc[i][j][1] + bb0) * qsc);
                Obuf[n * GP + r1]       = __float2half_rn((acc[i][j][2] + bb1) * qsc);
                Obuf[(n + 1) * GP + r1] = __float2half_rn((acc[i][j][3] + bb1) * qsc);
            }
        }
        __syncthreads();
#pragma unroll
        for (int r = 0; r < 2; r++) {
            const int idx = tid + 256 * r;
            const int n = idx >> 2, seg = idx & 3;
            // Q: unpermuted uint4 copy
            *(uint4*)&g_Qh[((size_t)b * NPIX + n0 + n) * CQK + seg * 8] =
                *(const uint4*)&Obuf[n * GP + seg * 8];
            // K: permuted pair stores (d along 32-dim)
#pragma unroll
            for (int pp = 0; pp < 4; pp++) {
                const int d = seg * 8 + pp * 2;
                *(__half2*)&g_Kh[((size_t)b * NPIX + n0 + n) * CQK + perm32(d)] =
                    *(const __half2*)&Obuf[n * GP + 32 + d];
            }
        }
    }
}

// ---------------------------------------------------------------------------
// Flash attention (R13 exact structure — measured best): static-max softmax,
// P = 2^S packed straight from QK accumulators; ones-MMA row sums;
// LDS.128 B-fragments (32-wide permuted K/V; 1 load = 2 MMAs);
// cp.async double-buffered. CTA: 64 queries, 8 warps.
// Warp w: query rows 16*(w&3).., channels 128*(w>>2)..
// ---------------------------------------------------------------------------
#define QTILE 64
#define KTILE 64
#define KP    32   // halves per K row (64B stride: LDS.128 conflict-free, no pad)
#define VP    96   // halves per V^T row (192B stride: LDS.128 conflict-free)
#define OFS_K0 0                       // 64*64   = 4096
#define OFS_K1 4096
#define OFS_V0 8192                    // 256*192 = 49152
#define OFS_V1 57344
#define ATT_SMEM 106496
#define OBP 66     // Obuf [256 c][66] floats (aliases buffers)

__global__ __launch_bounds__(256, 2) void attn_kernel(
    float* __restrict__ out, const float* __restrict__ gamma)
{
    extern __shared__ __align__(16) char sm[];
    const uint32_t smbase = (uint32_t)__cvta_generic_to_shared(sm);

    const int b   = blockIdx.y;
    const int q0  = blockIdx.x * QTILE;
    const int tid = threadIdx.x;
    const int w   = tid >> 5;
    const int lane = tid & 31;
    const int g = lane >> 2;
    const int t = lane & 3;

    const int qr = 16 * (w & 3);     // query row base for this warp
    const int ch = 128 * (w >> 2);   // channel half base

    const size_t bN = (size_t)b * NPIX;
    const size_t bC = (size_t)b * CDIM;

    // ---- Q fragments straight from global (one time; pre-scaled by log2e) ----
    uint32_t qa[2][4];
    {
        const __half* r0p = &g_Qh[(bN + q0 + qr + g) * CQK];
        const __half* r8p = r0p + 8 * CQK;
#pragma unroll
        for (int s = 0; s < 2; s++) {
            qa[s][0] = *(const uint32_t*)&r0p[16 * s + 2 * t];
            qa[s][1] = *(const uint32_t*)&r8p[16 * s + 2 * t];
            qa[s][2] = *(const uint32_t*)&r0p[16 * s + 8 + 2 * t];
            qa[s][3] = *(const uint32_t*)&r8p[16 * s + 8 + 2 * t];
        }
    }

    float acc[16][4];
#pragma unroll
    for (int j = 0; j < 16; j++)
#pragma unroll
        for (int k = 0; k < 4; k++) acc[j][k] = 0.f;

    // l carried as ones-MMA accumulators: ao0/ao1 -> row qr+g, ao2/ao3 -> row qr+8+g
    float ao0 = 0.f, ao1 = 0.f, ao2 = 0.f, ao3 = 0.f;

    // tile loader (cp.async, 16B chunks; gmem already permuted so copies are linear)
    const int krow = tid >> 2, kseg = tid & 3;
    auto issue_tile = [&](int buf, int m0g) {
        const uint32_t kb = smbase + (buf ? OFS_K1 : OFS_K0);
        const uint32_t vb = smbase + (buf ? OFS_V1 : OFS_V0);
        cpa16(kb + krow * (KP * 2) + kseg * 16,
              &g_Kh[(bN + m0g + krow) * CQK + kseg * 8]);
#pragma unroll
        for (int it = 0; it < 8; it++) {
            const int idx = tid + 256 * it;
            const int c = idx >> 3, seg = idx & 7;
            cpa16(vb + c * (VP * 2) + seg * 16,
                  &g_VhT[(bC + c) * NPIX + m0g + seg * 8]);
        }
        cpa_commit();
    };

    issue_tile(0, 0);

    for (int kt = 0; kt < NPIX / KTILE; kt++) {
        const int buf = kt & 1;
        cpa_wait0();
        __syncthreads();                       // tile ready; prev reads done
        if (kt + 1 < NPIX / KTILE)
            issue_tile(buf ^ 1, (kt + 1) * KTILE);

        const __half* Ks  = (const __half*)(sm + (buf ? OFS_K1 : OFS_K0));
        const __half* VsT = (const __half*)(sm + (buf ? OFS_V1 : OFS_V0));

        // ---- S = Q K^T : one LDS.128 per K row feeds both k-steps;
        //      P = 2^S packed straight into fp16 A-fragments (no max shift) ----
        uint32_t pa[4][4];
#pragma unroll
        for (int s = 0; s < 4; s++) {
            float s00, s01, s02, s03, s10, s11, s12, s13;
            {
                const uint4 kk = *(const uint4*)&Ks[(16 * s + g) * KP + 8 * t];
                float c0 = 0.f, c1 = 0.f, c2 = 0.f, c3 = 0.f;
                mma16816(c0, c1, c2, c3, qa[0][0], qa[0][1], qa[0][2], qa[0][3], kk.x, kk.y);
                mma16816(c0, c1, c2, c3, qa[1][0], qa[1][1], qa[1][2], qa[1][3], kk.z, kk.w);
                s00 = c0; s01 = c1; s02 = c2; s03 = c3;
            }
            {
                const uint4 kk = *(const uint4*)&Ks[(16 * s + 8 + g) * KP + 8 * t];
                float c0 = 0.f, c1 = 0.f, c2 = 0.f, c3 = 0.f;
                mma16816(c0, c1, c2, c3, qa[0][0], qa[0][1], qa[0][2], qa[0][3], kk.x, kk.y);
                mma16816(c0, c1, c2, c3, qa[1][0], qa[1][1], qa[1][2], qa[1][3], kk.z, kk.w);
                s10 = c0; s11 = c1; s12 = c2; s13 = c3;
            }
            pa[s][0] = ex2_h2(s00, s01);
            pa[s][1] = ex2_h2(s02, s03);
            pa[s][2] = ex2_h2(s10, s11);
            pa[s][3] = ex2_h2(s12, s13);
        }

        // ---- row sums via ones-MMA ----
#pragma unroll
        for (int s = 0; s < 4; s++)
            mma16816(ao0, ao1, ao2, ao3,
                     pa[s][0], pa[s][1], pa[s][2], pa[s][3], ONES_H2, ONES_H2);

        // ---- O += P V : one LDS.128 feeds 2 MMAs (32-wide permuted V) ----
#pragma unroll
        for (int sb = 0; sb < 2; sb++) {
#pragma unroll
            for (int jj = 0; jj < 16; jj++) {
                const uint4 vv =
                    *(const uint4*)&VsT[(ch + 8 * jj + g) * VP + 32 * sb + 8 * t];
                mma16816(acc[jj][0], acc[jj][1], acc[jj][2], acc[jj][3],
                         pa[2 * sb][0], pa[2 * sb][1], pa[2 * sb][2], pa[2 * sb][3],
                         vv.x, vv.y);
                mma16816(acc[jj][0], acc[jj][1], acc[jj][2], acc[jj][3],
                         pa[2 * sb + 1][0], pa[2 * sb + 1][1],
                         pa[2 * sb + 1][2], pa[2 * sb + 1][3],
                         vv.z, vv.w);
            }
        }
    }

    // ---- epilogue: scale, transpose via smem, coalesced store ----
    const float gamma0 = gamma[0];
    const float inv0 = gamma0 / ao0;   // row qr+g
    const float inv1 = gamma0 / ao2;   // row qr+8+g

    float* Obuf = (float*)sm;   // [256 c][OBP]
    __syncthreads();            // everyone done reading V buffers
#pragma unroll
    for (int jj = 0; jj < 16; jj++) {
        const int c = ch + 8 * jj + 2 * t;
        const int r0 = qr + g;
        const int r1 = r0 + 8;
        Obuf[c * OBP + r0]       = acc[jj][0] * inv0;
        Obuf[(c + 1) * OBP + r0] = acc[jj][1] * inv0;
        Obuf[c * OBP + r1]       = acc[jj][2] * inv1;
        Obuf[(c + 1) * OBP + r1] = acc[jj][3] * inv1;
    }
    __syncthreads();
#pragma unroll
    for (int it = 0; it < 64; it++) {
        const int idx = tid + 256 * it;
        const int c = idx >> 6, q = idx & 63;
        out[(bC + c) * NPIX + q0 + q] = Obuf[c * OBP + q];
    }
}

// ---------------------------------------------------------------------------
// Inputs: x, Wq, bq, Wk, bk, Wv, bv, gamma. Output: float32 [B,C,H,W].
// ---------------------------------------------------------------------------
extern "C" void kernel_launch(void* const* d_in, const int* in_sizes, int n_in,
                              void* d_out, int out_size)
{
    const float* x     = (const float*)d_in[0];
    const float* Wq    = (const float*)d_in[1];
    const float* bq    = (const float*)d_in[2];
    const float* Wk    = (const float*)d_in[3];
    const float* bk    = (const float*)d_in[4];
    const float* Wv    = (const float*)d_in[5];
    const float* bv    = (const float*)d_in[6];
    const float* gamma = (const float*)d_in[7];
    float* out = (float*)d_out;

    cudaFuncSetAttribute(attn_kernel,
                         cudaFuncAttributeMaxDynamicSharedMemorySize, ATT_SMEM);

    prep_kernel<<<dim3(NPIX / 32, CDIM / 32, BATCH), 256>>>(x, Wq, bq, Wk, bk, Wv, bv);
    proj_gemm_kernel<<<dim3(NPIX / 128, BATCH, 5), 256>>>();
    attn_kernel<<<dim3(NPIX / QTILE, BATCH), 256, ATT_SMEM>>>(out, gamma);
}